// round 5
// baseline (speedup 1.0000x reference)
#include <cuda_runtime.h>
#include <cuda_bf16.h>
#include <cstdint>

#define MAXL 16
#define S    16          // argmax slices per request
#define TPB  256
#define UNR  8           // independent float4 loads per thread (MLP)
#define MAXB 1024

// Zero-initialized scratch. g_count self-resets (last block per request writes
// 0 after finalizing) -> graph-replay safe.
__device__ unsigned long long g_slot[MAXB * S];
__device__ int                g_count[MAXB];

__global__ void __launch_bounds__(TPB, 4)
fused_rejection_kernel(
    const float* __restrict__ draft_probs,
    const float* __restrict__ target_probs,
    const float* __restrict__ uniform_probs,
    const int*   __restrict__ draft_token_ids,
    const int*   __restrict__ cu,
    const int*   __restrict__ bonus,
    float*       __restrict__ out,
    int V, int NT, int L)
{
    const int s   = blockIdx.x;   // slice
    const int b   = blockIdx.y;   // request
    const int tid = threadIdx.x;

    __shared__ int   s_dids[MAXL];
    __shared__ float s_tp[MAXL], s_dp[MAXL], s_u[MAXL];
    __shared__ int   s_last, s_rejected, s_write_col, s_recrow;
    __shared__ unsigned long long s_warp[TPB / 32];

    const int prev   = (b == 0) ? 0 : __ldg(&cu[b - 1]);
    const int ndraft = __ldg(&cu[b]) - prev;
    const int n      = ndraft < L ? ndraft : L;

    // Redundant per-slice gather (replicas L2-hit); overlaps the latency chain
    // with other blocks' streaming.
    if (tid < n && n > 0) {
        long long gidx = (long long)(prev + tid);
        int d = __ldg(&draft_token_ids[gidx]);
        s_dids[tid] = d;
        s_tp[tid] = __ldg(&target_probs[gidx * (long long)V + d]);
        s_dp[tid] = __ldg(&draft_probs [gidx * (long long)V + d]);
        s_u [tid] = __ldg(&uniform_probs[gidx]);
    }
    __syncthreads();

    if (tid == 0) {
        float pi = 1.0f, U = 1.0f;
        int last = -1;
        for (int i = 0; i < n; i++) {
            float dp = s_dp[i];
            float r  = (dp > 0.0f) ? (s_tp[i] / dp) : 1.0f;
            pi = fminf(pi * r, 1.0f);
            U  = U * s_u[i];
            if ((dp > 0.0f) && (pi >= U)) last = i;
        }
        int rejected = (ndraft > 0) && (last != ndraft - 1);
        int rr = prev + last + 1;
        s_recrow    = max(0, min(rr, NT - 1));
        s_last      = last;
        s_rejected  = rejected;
        s_write_col = rejected ? (last + 1) : n;
    }
    __syncthreads();

    if (s == 0 && tid <= L) {
        int val = (tid < L && tid <= s_last) ? s_dids[tid] : -1;
        if (tid == s_write_col)
            val = s_rejected ? -1 : __ldg(&bonus[b]);
        out[b * (L + 1) + tid] = (float)val;
    }

    if (!s_rejected) return;

    // ---- streaming argmax, high-MLP version ----
    const int chunk = (((V + S - 1) / S) + 3) & ~3;
    const int start = s * chunk;
    const int end   = min(V, start + chunk);
    const float* __restrict__ row  = target_probs + (long long)s_recrow * V;
    const float4* __restrict__ row4 = (const float4*)(row + start);
    const int nv4 = (end - start) >> 2;

    // 4 independent running-max chains (uint bit compare: valid, probs >= 0).
    // Strict '>' + ascending per-thread index keeps the FIRST max per chain.
    unsigned m0 = 0, m1 = 0, m2 = 0, m3 = 0;
    unsigned i0 = 0xFFFFFFFFu, i1 = 0xFFFFFFFFu, i2 = 0xFFFFFFFFu, i3 = 0xFFFFFFFFu;

    for (int j0 = 0; j0 < nv4; j0 += TPB * UNR) {
        float4 v[UNR];
        int    p[UNR];
        #pragma unroll
        for (int u = 0; u < UNR; u++) {           // issue all loads first (MLP)
            p[u] = j0 + u * TPB + tid;
            if (p[u] < nv4) v[u] = row4[p[u]];
        }
        #pragma unroll
        for (int u = 0; u < UNR; u++) {
            if (p[u] < nv4) {
                unsigned gi = (unsigned)(start + (p[u] << 2));
                unsigned bx = __float_as_uint(v[u].x);
                unsigned by = __float_as_uint(v[u].y);
                unsigned bz = __float_as_uint(v[u].z);
                unsigned bw = __float_as_uint(v[u].w);
                if (bx > m0) { m0 = bx; i0 = gi;     }
                if (by > m1) { m1 = by; i1 = gi + 1; }
                if (bz > m2) { m2 = bz; i2 = gi + 2; }
                if (bw > m3) { m3 = bw; i3 = gi + 3; }
            }
        }
    }

    // Merge 4 chains with full packed keys (tie-break -> smallest index).
    unsigned long long best, k;
    best = ((unsigned long long)m0 << 32) | (0xFFFFFFFFu - i0);
    k    = ((unsigned long long)m1 << 32) | (0xFFFFFFFFu - i1); if (k > best) best = k;
    k    = ((unsigned long long)m2 << 32) | (0xFFFFFFFFu - i2); if (k > best) best = k;
    k    = ((unsigned long long)m3 << 32) | (0xFFFFFFFFu - i3); if (k > best) best = k;

    // Scalar tail (V not divisible by 4 per slice — not hit for V=128000).
    for (int i = start + (nv4 << 2) + tid; i < end; i += TPB) {
        k = ((unsigned long long)__float_as_uint(row[i]) << 32) |
            (0xFFFFFFFFu - (unsigned)i);
        if (k > best) best = k;
    }

    #pragma unroll
    for (int off = 16; off > 0; off >>= 1) {
        unsigned long long o = __shfl_down_sync(0xFFFFFFFFu, best, off);
        if (o > best) best = o;
    }
    if ((tid & 31) == 0) s_warp[tid >> 5] = best;
    __syncthreads();

    if (tid < 32) {
        unsigned long long v = (tid < (TPB / 32)) ? s_warp[tid] : 0ull;
        #pragma unroll
        for (int off = 16; off > 0; off >>= 1) {
            unsigned long long o = __shfl_down_sync(0xFFFFFFFFu, v, off);
            if (o > v) v = o;
        }
        if (tid == 0) {
            g_slot[b * S + s] = v;
            __threadfence();
            int old = atomicAdd(&g_count[b], 1);
            if (old == S - 1) {
                unsigned long long m = 0ull;
                #pragma unroll
                for (int j = 0; j < S; j++) {
                    unsigned long long w = g_slot[b * S + j];
                    if (w > m) m = w;
                }
                int rec = (int)(0xFFFFFFFFu - (unsigned)(m & 0xFFFFFFFFull));
                out[b * (L + 1) + s_write_col] = (float)rec;
                g_count[b] = 0;   // self-reset for next replay
            }
        }
    }
}

extern "C" void kernel_launch(void* const* d_in, const int* in_sizes, int n_in,
                              void* d_out, int out_size) {
    const float* draft_probs     = (const float*)d_in[0];
    const float* target_probs    = (const float*)d_in[1];
    const float* uniform_probs   = (const float*)d_in[2];
    const int*   draft_token_ids = (const int*)  d_in[3];
    const int*   cu              = (const int*)  d_in[4];
    const int*   bonus           = (const int*)  d_in[5];
    float*       out             = (float*)d_out;

    const int NT = in_sizes[2];
    const int V  = in_sizes[0] / NT;
    const int B  = in_sizes[4];
    const int L  = out_size / B - 1;

    fused_rejection_kernel<<<dim3(S, B), TPB>>>(
        draft_probs, target_probs, uniform_probs,
        draft_token_ids, cu, bonus, out, V, NT, L);
}

// round 7
// speedup vs baseline: 1.2786x; 1.2786x over previous
#include <cuda_runtime.h>
#include <cuda_bf16.h>
#include <cstdint>

#define MAXL 16
#define S    25          // slices: 32000 float4 / 25 = 1280 = 256*5 (exact fit)
#define TPB  256
#define UNR  5           // unconditional float4 loads per thread
#define MAXB 1024

// Zero-initialized scratch; g_count self-resets -> graph-replay safe.
__device__ unsigned long long g_slot[MAXB * S];
__device__ int                g_count[MAXB];

__global__ void __launch_bounds__(TPB)
fused_rejection_kernel(
    const float* __restrict__ draft_probs,
    const float* __restrict__ target_probs,
    const float* __restrict__ uniform_probs,
    const int*   __restrict__ draft_token_ids,
    const int*   __restrict__ cu,
    const int*   __restrict__ bonus,
    float*       __restrict__ out,
    int V, int NT, int L)
{
    const int s   = blockIdx.x;   // slice
    const int b   = blockIdx.y;   // request
    const int tid = threadIdx.x;

    __shared__ int   s_dids[MAXL];
    __shared__ float s_tp[MAXL], s_dp[MAXL], s_u[MAXL];
    __shared__ int   s_last, s_rejected, s_write_col, s_recrow;
    __shared__ unsigned long long s_warp[TPB / 32];

    const int prev   = (b == 0) ? 0 : __ldg(&cu[b - 1]);
    const int ndraft = __ldg(&cu[b]) - prev;
    const int n      = ndraft < L ? ndraft : L;

    // Redundant per-slice gather (replicas L2-hit; overlaps with streaming).
    if (tid < n && n > 0) {
        long long gidx = (long long)(prev + tid);
        int d = __ldg(&draft_token_ids[gidx]);
        s_dids[tid] = d;
        s_tp[tid] = __ldg(&target_probs[gidx * (long long)V + d]);
        s_dp[tid] = __ldg(&draft_probs [gidx * (long long)V + d]);
        s_u [tid] = __ldg(&uniform_probs[gidx]);
    }
    __syncthreads();

    if (tid == 0) {
        float pi = 1.0f, U = 1.0f;
        int last = -1;
        for (int i = 0; i < n; i++) {
            float dp = s_dp[i];
            float r  = (dp > 0.0f) ? (s_tp[i] / dp) : 1.0f;
            pi = fminf(pi * r, 1.0f);
            U  = U * s_u[i];
            if ((dp > 0.0f) && (pi >= U)) last = i;
        }
        int rejected = (ndraft > 0) && (last != ndraft - 1);
        int rr = prev + last + 1;
        s_recrow    = max(0, min(rr, NT - 1));
        s_last      = last;
        s_rejected  = rejected;
        s_write_col = rejected ? (last + 1) : n;
    }
    __syncthreads();

    if (s == 0 && tid <= L) {
        int val = (tid < L && tid <= s_last) ? s_dids[tid] : -1;
        if (tid == s_write_col)
            val = s_rejected ? -1 : __ldg(&bonus[b]);
        out[b * (L + 1) + tid] = (float)val;
    }

    if (!s_rejected) return;

    // ---- streaming argmax over this slice of the recovery row ----
    const int nv4_tot = V >> 2;                       // total float4 in row
    const int chunk4  = (nv4_tot + S - 1) / S;        // =1280 for V=128000
    const int start4  = s * chunk4;
    const int end4    = min(nv4_tot, start4 + chunk4);
    const int n4      = end4 - start4;

    const float4* __restrict__ row4 =
        (const float4*)target_probs + (long long)s_recrow * nv4_tot + start4;

    // 4 independent running-max chains (uint bit compare valid: probs >= 0).
    // Strict '>' with ascending per-thread index keeps the FIRST max per chain.
    unsigned m0 = 0, m1 = 0, m2 = 0, m3 = 0;
    unsigned i0 = 0xFFFFFFFFu, i1 = 0xFFFFFFFFu, i2 = 0xFFFFFFFFu, i3 = 0xFFFFFFFFu;

    int j0 = 0;
    // Unguarded, named-register batches of UNR loads (all issued before use).
    for (; j0 + TPB * UNR <= n4; j0 += TPB * UNR) {
        const float4* p = row4 + j0 + tid;
        float4 v0 = p[0 * TPB];
        float4 v1 = p[1 * TPB];
        float4 v2 = p[2 * TPB];
        float4 v3 = p[3 * TPB];
        float4 v4 = p[4 * TPB];
        unsigned g0 = (unsigned)((start4 + j0 + 0 * TPB + tid) << 2);
        unsigned g1 = (unsigned)((start4 + j0 + 1 * TPB + tid) << 2);
        unsigned g2 = (unsigned)((start4 + j0 + 2 * TPB + tid) << 2);
        unsigned g3 = (unsigned)((start4 + j0 + 3 * TPB + tid) << 2);
        unsigned g4 = (unsigned)((start4 + j0 + 4 * TPB + tid) << 2);
        unsigned t;
        t = __float_as_uint(v0.x); if (t > m0) { m0 = t; i0 = g0;     }
        t = __float_as_uint(v0.y); if (t > m1) { m1 = t; i1 = g0 + 1; }
        t = __float_as_uint(v0.z); if (t > m2) { m2 = t; i2 = g0 + 2; }
        t = __float_as_uint(v0.w); if (t > m3) { m3 = t; i3 = g0 + 3; }
        t = __float_as_uint(v1.x); if (t > m0) { m0 = t; i0 = g1;     }
        t = __float_as_uint(v1.y); if (t > m1) { m1 = t; i1 = g1 + 1; }
        t = __float_as_uint(v1.z); if (t > m2) { m2 = t; i2 = g1 + 2; }
        t = __float_as_uint(v1.w); if (t > m3) { m3 = t; i3 = g1 + 3; }
        t = __float_as_uint(v2.x); if (t > m0) { m0 = t; i0 = g2;     }
        t = __float_as_uint(v2.y); if (t > m1) { m1 = t; i1 = g2 + 1; }
        t = __float_as_uint(v2.z); if (t > m2) { m2 = t; i2 = g2 + 2; }
        t = __float_as_uint(v2.w); if (t > m3) { m3 = t; i3 = g2 + 3; }
        t = __float_as_uint(v3.x); if (t > m0) { m0 = t; i0 = g3;     }
        t = __float_as_uint(v3.y); if (t > m1) { m1 = t; i1 = g3 + 1; }
        t = __float_as_uint(v3.z); if (t > m2) { m2 = t; i2 = g3 + 2; }
        t = __float_as_uint(v3.w); if (t > m3) { m3 = t; i3 = g3 + 3; }
        t = __float_as_uint(v4.x); if (t > m0) { m0 = t; i0 = g4;     }
        t = __float_as_uint(v4.y); if (t > m1) { m1 = t; i1 = g4 + 1; }
        t = __float_as_uint(v4.z); if (t > m2) { m2 = t; i2 = g4 + 2; }
        t = __float_as_uint(v4.w); if (t > m3) { m3 = t; i3 = g4 + 3; }
    }
    // Guarded remainder (empty for V=128000 with S=25).
    for (int j = j0 + tid; j < n4; j += TPB) {
        float4 v = row4[j];
        unsigned gi = (unsigned)((start4 + j) << 2);
        unsigned t;
        t = __float_as_uint(v.x); if (t > m0) { m0 = t; i0 = gi;     }
        t = __float_as_uint(v.y); if (t > m1) { m1 = t; i1 = gi + 1; }
        t = __float_as_uint(v.z); if (t > m2) { m2 = t; i2 = gi + 2; }
        t = __float_as_uint(v.w); if (t > m3) { m3 = t; i3 = gi + 3; }
    }

    // Merge chains via packed keys (tie-break -> smallest global index).
    unsigned long long best, k;
    best = ((unsigned long long)m0 << 32) | (0xFFFFFFFFu - i0);
    k    = ((unsigned long long)m1 << 32) | (0xFFFFFFFFu - i1); if (k > best) best = k;
    k    = ((unsigned long long)m2 << 32) | (0xFFFFFFFFu - i2); if (k > best) best = k;
    k    = ((unsigned long long)m3 << 32) | (0xFFFFFFFFu - i3); if (k > best) best = k;

    // Scalar tail for V%4 != 0 (slice S-1 only; empty here).
    if (s == S - 1) {
        const float* row = target_probs + (long long)s_recrow * V;
        for (int i = (nv4_tot << 2) + tid; i < V; i += TPB) {
            k = ((unsigned long long)__float_as_uint(row[i]) << 32) |
                (0xFFFFFFFFu - (unsigned)i);
            if (k > best) best = k;
        }
    }

    #pragma unroll
    for (int off = 16; off > 0; off >>= 1) {
        unsigned long long o = __shfl_down_sync(0xFFFFFFFFu, best, off);
        if (o > best) best = o;
    }
    if ((tid & 31) == 0) s_warp[tid >> 5] = best;
    __syncthreads();

    if (tid < 32) {
        unsigned long long v = (tid < (TPB / 32)) ? s_warp[tid] : 0ull;
        #pragma unroll
        for (int off = 16; off > 0; off >>= 1) {
            unsigned long long o = __shfl_down_sync(0xFFFFFFFFu, v, off);
            if (o > v) v = o;
        }
        if (tid == 0) {
            g_slot[b * S + s] = v;
            __threadfence();
            int old = atomicAdd(&g_count[b], 1);
            if (old == S - 1) {
                unsigned long long m = 0ull;
                #pragma unroll
                for (int j = 0; j < S; j++) {
                    unsigned long long w = g_slot[b * S + j];
                    if (w > m) m = w;
                }
                int rec = (int)(0xFFFFFFFFu - (unsigned)(m & 0xFFFFFFFFull));
                out[b * (L + 1) + s_write_col] = (float)rec;
                g_count[b] = 0;   // self-reset for next replay
            }
        }
    }
}

extern "C" void kernel_launch(void* const* d_in, const int* in_sizes, int n_in,
                              void* d_out, int out_size) {
    const float* draft_probs     = (const float*)d_in[0];
    const float* target_probs    = (const float*)d_in[1];
    const float* uniform_probs   = (const float*)d_in[2];
    const int*   draft_token_ids = (const int*)  d_in[3];
    const int*   cu              = (const int*)  d_in[4];
    const int*   bonus           = (const int*)  d_in[5];
    float*       out             = (float*)d_out;

    const int NT = in_sizes[2];
    const int V  = in_sizes[0] / NT;
    const int B  = in_sizes[4];
    const int L  = out_size / B - 1;

    fused_rejection_kernel<<<dim3(S, B), TPB>>>(
        draft_probs, target_probs, uniform_probs,
        draft_token_ids, cu, bonus, out, V, NT, L);
}